// round 3
// baseline (speedup 1.0000x reference)
#include <cuda_runtime.h>

// PaDiM Mahalanobis score map, GB300 sm_103a.
// Inputs (metadata order):
//   d_in[0] fmaps  f32 (8,448,56,56)
//   d_in[1] select int32 (100)
//   d_in[2] mean   f32 (100,56,56)
//   d_in[3] cov    f32 (100,100,56,56)  -- symmetric per pixel
//   d_in[4] min_score f32 scalar
//   d_in[5] max_score f32 scalar
// Output: f32 (8,224,224)

#define CT   448
#define C    100
#define HW   3136      // 56*56
#define NB   8
#define P    64        // pixels per block
#define NTHR 256
#define CHW  (C*HW)    // 313600

typedef unsigned long long u64;

// partial s^2 sums: [chunk][n][pixel]
__device__ float g_part[3 * NB * HW];

// Balanced partition of the 25 c-blocks (4 channels each) into 3 chunks.
// Main-loop d-steps per k: 96-4k. Chunks sum to ~400 each.
__constant__ unsigned char c_klist[25] = {
    0, 1, 2, 3, 14,                     // 96+92+88+84+40 = 400
    4, 5, 6, 7, 8, 15, 23,              // 80+76+72+68+64+36+4 = 400
    9, 10, 11, 12, 13, 16, 17, 18, 19, 20, 21, 22, 24  // = 400
};
__constant__ int c_koff[4] = {0, 5, 12, 25};

__device__ __forceinline__ u64 pk2(float lo, float hi) {
    u64 r; asm("mov.b64 %0, {%1, %2};" : "=l"(r) : "f"(lo), "f"(hi)); return r;
}
__device__ __forceinline__ float2 upk2(u64 a) {
    float2 f; asm("mov.b64 {%0, %1}, %2;" : "=f"(f.x), "=f"(f.y) : "l"(a)); return f;
}
__device__ __forceinline__ u64 add2(u64 a, u64 b) {
    u64 r; asm("add.rn.f32x2 %0, %1, %2;" : "=l"(r) : "l"(a), "l"(b)); return r;
}
__device__ __forceinline__ u64 mul2(u64 a, u64 b) {
    u64 r; asm("mul.rn.f32x2 %0, %1, %2;" : "=l"(r) : "l"(a), "l"(b)); return r;
}
__device__ __forceinline__ u64 fma2(u64 a, u64 b, u64 c) {
    u64 r; asm("fma.rn.f32x2 %0, %1, %2, %3;" : "=l"(r) : "l"(a), "l"(b), "l"(c)); return r;
}

extern __shared__ float xs[];   // [C][P][8] = 100*64*8 floats = 204800 B

__global__ void __launch_bounds__(NTHR, 1) padim_main(
    const float* __restrict__ fmaps,
    const int*   __restrict__ sel,
    const float* __restrict__ mean,
    const float* __restrict__ cov)
{
    __shared__ int sel_s[C];
    const int tid   = threadIdx.x;
    const int pbase = blockIdx.x * P;
    const int chunk = blockIdx.y;

    if (tid < C) sel_s[tid] = sel[tid];
    __syncthreads();

    // Build x tile: x[c][p][n] = fmaps[n, sel[c], pix] - mean[c, pix]
    for (int i = tid; i < C * NB * P; i += NTHR) {
        int p = i & (P - 1);
        int n = (i >> 6) & 7;
        int c = i >> 9;
        float f = fmaps[(n * CT + sel_s[c]) * HW + pbase + p];
        float m = mean[c * HW + pbase + p];
        xs[(c * P + p) * 8 + n] = f - m;
    }
    __syncthreads();

    const int p  = tid >> 2;    // pixel within tile (0..63)
    const int np = tid & 3;     // n-pair index: handles n = 2np, 2np+1
    const int pg = pbase + p;   // global pixel

    u64 accA = 0ull, accB = 0ull;   // packed (n0, n1) accumulators

    const int kb = c_koff[chunk], ke = c_koff[chunk + 1];
    for (int ki = kb; ki < ke; ++ki) {
        const int c0 = 4 * (int)c_klist[ki];

        u64 xc[4], xc2[4];
        #pragma unroll
        for (int j = 0; j < 4; ++j) {
            xc[j]  = *(const u64*)&xs[((c0 + j) * P + p) * 8 + 2 * np];
            xc2[j] = add2(xc[j], xc[j]);      // pre-fold the off-diagonal factor 2
        }

        const float* cvb = cov + c0 * CHW + pg;

        // diagonal 4x4 micro-block: pairs (c0+j, c0+dd), j <= dd
        #pragma unroll
        for (int dd = 0; dd < 4; ++dd) {
            const float* cd = cvb + (c0 + dd) * HW;
            #pragma unroll
            for (int j = 0; j <= dd; ++j) {
                float v = cd[j * CHW];
                u64 t = (j == dd) ? mul2(xc[dd], xc[dd]) : mul2(xc2[j], xc[dd]);
                if (((dd + j) & 1) == 0) accA = fma2(pk2(v, v), t, accA);
                else                     accB = fma2(pk2(v, v), t, accB);
            }
        }

        // main sweep: d = c0+4 .. 99, 4 pairs per step (count divisible by 4)
        const float* cv = cvb + (c0 + 4) * HW;
        #pragma unroll 4
        for (int d = c0 + 4; d < C; ++d) {
            u64 xd = *(const u64*)&xs[(d * P + p) * 8 + 2 * np];
            float v0 = cv[0];
            float v1 = cv[CHW];
            float v2 = cv[2 * CHW];
            float v3 = cv[3 * CHW];
            accA = fma2(pk2(v0, v0), mul2(xc2[0], xd), accA);
            accB = fma2(pk2(v1, v1), mul2(xc2[1], xd), accB);
            accA = fma2(pk2(v2, v2), mul2(xc2[2], xd), accA);
            accB = fma2(pk2(v3, v3), mul2(xc2[3], xd), accB);
            cv += HW;
        }
    }

    float2 r = upk2(add2(accA, accB));
    g_part[(chunk * NB + 2 * np    ) * HW + pg] = r.x;
    g_part[(chunk * NB + 2 * np + 1) * HW + pg] = r.y;
}

// sum partials -> sqrt -> half-pixel bilinear x4 -> normalize
__global__ void padim_finalize(float* __restrict__ out,
                               const float* __restrict__ minp,
                               const float* __restrict__ maxp)
{
    int idx = blockIdx.x * blockDim.x + threadIdx.x;
    if (idx >= NB * 224 * 224) return;
    int n = idx / (224 * 224);
    int r = idx % (224 * 224);
    int y = r / 224, x = r % 224;

    float sy = y * 0.25f - 0.375f;
    float sx = x * 0.25f - 0.375f;
    float fy = floorf(sy), fx = floorf(sx);
    float wy = sy - fy, wx = sx - fx;
    int y0 = (int)fy, x0 = (int)fx;
    int y1 = min(y0 + 1, 55); y0 = max(y0, 0);
    int x1 = min(x0 + 1, 55); x0 = max(x0, 0);

    int nb = n * HW;
    #define SVAL(yy, xx) ({                                            \
        int o = nb + (yy) * 56 + (xx);                                 \
        float s2 = g_part[o] + g_part[NB * HW + o] + g_part[2 * NB * HW + o]; \
        sqrtf(fmaxf(s2, 0.0f)); })

    float v00 = SVAL(y0, x0), v01 = SVAL(y0, x1);
    float v10 = SVAL(y1, x0), v11 = SVAL(y1, x1);
    #undef SVAL

    float v0 = v00 + wx * (v01 - v00);
    float v1 = v10 + wx * (v11 - v10);
    float v  = v0  + wy * (v1  - v0);

    float mn = *minp, mx = *maxp;
    out[idx] = (v - mn) / (mx - mn);
}

extern "C" void kernel_launch(void* const* d_in, const int* in_sizes, int n_in,
                              void* d_out, int out_size)
{
    const float* fmaps = (const float*)d_in[0];
    const int*   sel   = (const int*)  d_in[1];
    const float* mean  = (const float*)d_in[2];
    const float* cov   = (const float*)d_in[3];
    const float* mn    = (const float*)d_in[4];
    const float* mx    = (const float*)d_in[5];
    float* out = (float*)d_out;

    const int smem = C * P * 8 * sizeof(float);  // 204800 B
    cudaFuncSetAttribute(padim_main, cudaFuncAttributeMaxDynamicSharedMemorySize, smem);

    dim3 grid(HW / P, 3);
    padim_main<<<grid, NTHR, smem>>>(fmaps, sel, mean, cov);

    int total = NB * 224 * 224;
    padim_finalize<<<(total + 255) / 256, 256>>>(out, mn, mx);
}

// round 4
// speedup vs baseline: 2.2901x; 2.2901x over previous
#include <cuda_runtime.h>

// PaDiM Mahalanobis score map, GB300 sm_103a.
// Inputs (metadata order):
//   d_in[0] fmaps  f32 (8,448,56,56)
//   d_in[1] select int32 (100)
//   d_in[2] mean   f32 (100,56,56)
//   d_in[3] cov    f32 (100,100,56,56)  -- symmetric per pixel (A A^T)
//   d_in[4] min_score f32 scalar
//   d_in[5] max_score f32 scalar
// Output: f32 (8,224,224)

#define CT   448
#define C    100
#define HW   3136      // 56*56
#define NB   8
#define P    64        // pixels per block
#define P2   32        // pixel pairs per block
#define NTHR 512
#define CHW  (C*HW)    // 313600

typedef unsigned long long u64;

// partial s^2 sums: [chunk][n][pixel]
__device__ float g_part[3 * NB * HW];
// sqrt'ed score map: [n][pixel]
__device__ float g_smap[NB * HW];

__device__ __forceinline__ u64 pk2(float lo, float hi) {
    u64 r; asm("mov.b64 %0, {%1, %2};" : "=l"(r) : "f"(lo), "f"(hi)); return r;
}
__device__ __forceinline__ float2 upk2(u64 a) {
    float2 f; asm("mov.b64 {%0, %1}, %2;" : "=f"(f.x), "=f"(f.y) : "l"(a)); return f;
}
__device__ __forceinline__ u64 add2(u64 a, u64 b) {
    u64 r; asm("add.rn.f32x2 %0, %1, %2;" : "=l"(r) : "l"(a), "l"(b)); return r;
}
__device__ __forceinline__ u64 mul2(u64 a, u64 b) {
    u64 r; asm("mul.rn.f32x2 %0, %1, %2;" : "=l"(r) : "l"(a), "l"(b)); return r;
}
__device__ __forceinline__ u64 fma2(u64 a, u64 b, u64 c) {
    u64 r; asm("fma.rn.f32x2 %0, %1, %2, %3;" : "=l"(r) : "l"(a), "l"(b), "l"(c)); return r;
}

// x tile layout: [c][np][p2][4]  where the 4 floats are
//   (pixel 2*p2 : n=2np, n=2np+1, pixel 2*p2+1 : n=2np, n=2np+1)
// size = 100*4*32*4 floats = 204800 B
extern __shared__ float xs[];

__device__ __forceinline__ int xidx(int c, int np, int p2) {
    return ((c * 4 + np) * P2 + p2) * 4;
}

__global__ void __launch_bounds__(NTHR, 1) padim_main(
    const float* __restrict__ fmaps,
    const int*   __restrict__ sel,
    const float* __restrict__ mean,
    const float* __restrict__ cov)
{
    __shared__ int sel_s[C];
    const int tid   = threadIdx.x;
    const int pbase = blockIdx.x * P;
    const int chunk = blockIdx.y;

    if (tid < C) sel_s[tid] = sel[tid];
    __syncthreads();

    // Build x tile
    for (int i = tid; i < C * NB * P; i += NTHR) {
        int p = i & (P - 1);
        int n = (i >> 6) & 7;
        int c = i >> 9;
        float v = fmaps[(n * CT + sel_s[c]) * HW + pbase + p]
                - mean[c * HW + pbase + p];
        xs[xidx(c, n >> 1, p >> 1) + (p & 1) * 2 + (n & 1)] = v;
    }
    __syncthreads();

    // thread mapping: warp = 32 consecutive p2 (same np, same ds)
    const int p2 = tid & 31;
    const int np = (tid >> 5) & 3;
    const int ds = tid >> 7;            // 0..3
    const int slice = chunk * 4 + ds;   // 0..11
    const int pg = pbase + 2 * p2;      // first pixel of the pair

    u64 accA = 0ull, accB = 0ull;       // packed (n0,n1) accum for pixel A / B

    // ---- main off-diagonal sweep: global steps [slice*100, slice*100+100) ----
    // base(k) = 2k(49-k); step g in k maps to d = 4k+4 + (g - base(k))
    int g = slice * 100, gend = g + 100;
    int k = 0;
    while (2 * (k + 1) * (48 - k) <= g) ++k;

    while (g < gend) {
        const int c0 = 4 * k;
        const int d0 = 4 * k + 4 + (g - 2 * k * (49 - k));
        const int nst = min(100 - d0, gend - g);

        // xc*2 (off-diagonal factor folded), both pixels
        u64 xc2A[4], xc2B[4];
        #pragma unroll
        for (int j = 0; j < 4; ++j) {
            float4 xq = *(const float4*)&xs[xidx(c0 + j, np, p2)];
            xc2A[j] = pk2(xq.x + xq.x, xq.y + xq.y);
            xc2B[j] = pk2(xq.z + xq.z, xq.w + xq.w);
        }

        u64 lA0=0,lA1=0,lA2=0,lA3=0, lB0=0,lB1=0,lB2=0,lB3=0;
        const float* cb = cov + (size_t)c0 * CHW + (size_t)d0 * HW + pg;

        #pragma unroll 4
        for (int s = 0; s < nst; ++s) {
            float2 v0 = *(const float2*)(cb);
            float2 v1 = *(const float2*)(cb + CHW);
            float2 v2 = *(const float2*)(cb + 2 * CHW);
            float2 v3 = *(const float2*)(cb + 3 * CHW);
            float4 xq = *(const float4*)&xs[xidx(d0 + s, np, p2)];
            u64 xdA = pk2(xq.x, xq.y);
            u64 xdB = pk2(xq.z, xq.w);
            lA0 = fma2(pk2(v0.x, v0.x), xdA, lA0);
            lB0 = fma2(pk2(v0.y, v0.y), xdB, lB0);
            lA1 = fma2(pk2(v1.x, v1.x), xdA, lA1);
            lB1 = fma2(pk2(v1.y, v1.y), xdB, lB1);
            lA2 = fma2(pk2(v2.x, v2.x), xdA, lA2);
            lB2 = fma2(pk2(v2.y, v2.y), xdB, lB2);
            lA3 = fma2(pk2(v3.x, v3.x), xdA, lA3);
            lB3 = fma2(pk2(v3.y, v3.y), xdB, lB3);
            cb += HW;
        }

        accA = fma2(xc2A[0], lA0, accA); accB = fma2(xc2B[0], lB0, accB);
        accA = fma2(xc2A[1], lA1, accA); accB = fma2(xc2B[1], lB1, accB);
        accA = fma2(xc2A[2], lA2, accA); accB = fma2(xc2B[2], lB2, accB);
        accA = fma2(xc2A[3], lA3, accA); accB = fma2(xc2B[3], lB3, accB);

        g += nst;
        if (d0 + nst == 100) ++k;
    }

    // ---- diagonal 4x4 micro-blocks: block kk handled by slice kk%12 ----
    for (int kk = slice; kk < 25; kk += 12) {
        const int c0 = 4 * kk;
        u64 xA[4], xB[4], x2A[4], x2B[4];
        #pragma unroll
        for (int j = 0; j < 4; ++j) {
            float4 xq = *(const float4*)&xs[xidx(c0 + j, np, p2)];
            xA[j]  = pk2(xq.x, xq.y);
            xB[j]  = pk2(xq.z, xq.w);
            x2A[j] = add2(xA[j], xA[j]);
            x2B[j] = add2(xB[j], xB[j]);
        }
        const float* cb = cov + (size_t)c0 * CHW + (size_t)c0 * HW + pg;
        #pragma unroll
        for (int dd = 0; dd < 4; ++dd) {
            #pragma unroll
            for (int j = 0; j <= dd; ++j) {
                float2 v = *(const float2*)(cb + (size_t)j * CHW + (size_t)dd * HW);
                u64 tA = (j == dd) ? mul2(xA[dd], xA[dd]) : mul2(x2A[j], xA[dd]);
                u64 tB = (j == dd) ? mul2(xB[dd], xB[dd]) : mul2(x2B[j], xB[dd]);
                accA = fma2(pk2(v.x, v.x), tA, accA);
                accB = fma2(pk2(v.y, v.y), tB, accB);
            }
        }
    }

    // ---- in-block reduction over the 4 d-slices ----
    __syncthreads();                // all xs reads done
    u64* red = (u64*)xs;
    red[tid * 2]     = accA;
    red[tid * 2 + 1] = accB;
    __syncthreads();

    if (tid < 128) {
        u64 a = red[tid * 2], b = red[tid * 2 + 1];
        #pragma unroll
        for (int s2 = 1; s2 < 4; ++s2) {
            a = add2(a, red[(tid + 128 * s2) * 2]);
            b = add2(b, red[(tid + 128 * s2) * 2 + 1]);
        }
        float2 rA = upk2(a), rB = upk2(b);
        int base = (chunk * NB + 2 * np) * HW + pg;
        g_part[base]          = rA.x;
        g_part[base + HW]     = rA.y;
        g_part[base + 1]      = rB.x;
        g_part[base + HW + 1] = rB.y;
    }
}

// sum 3 partials -> sqrt
__global__ void padim_smap()
{
    int i = blockIdx.x * blockDim.x + threadIdx.x;
    if (i >= NB * HW) return;
    float s2 = g_part[i] + g_part[NB * HW + i] + g_part[2 * NB * HW + i];
    g_smap[i] = sqrtf(fmaxf(s2, 0.0f));
}

// half-pixel bilinear x4 + normalize; 4 output x per thread (one source quad)
__global__ void padim_finalize(float* __restrict__ out,
                               const float* __restrict__ minp,
                               const float* __restrict__ maxp)
{
    int idx = blockIdx.x * blockDim.x + threadIdx.x;  // over NB*224*56
    if (idx >= NB * 224 * 56) return;
    int q = idx % 56;
    int t = idx / 56;
    int y = t % 224;
    int n = t / 224;

    float sy = y * 0.25f - 0.375f;
    float fy = floorf(sy);
    float wy = sy - fy;
    int y0 = max((int)fy, 0);
    int y1 = min((int)fy + 1, 55);
    int cm = max(q - 1, 0);
    int cp = min(q + 1, 55);

    const float* s = g_smap + n * HW;
    float sm0 = s[y0 * 56 + cm], sm1 = s[y1 * 56 + cm];
    float s00 = s[y0 * 56 + q],  s01 = s[y1 * 56 + q];
    float sp0 = s[y0 * 56 + cp], sp1 = s[y1 * 56 + cp];

    float vm = sm0 + wy * (sm1 - sm0);
    float v0 = s00 + wy * (s01 - s00);
    float vp = sp0 + wy * (sp1 - sp0);

    float mn  = *minp;
    float inv = 1.0f / (*maxp - mn);

    float4 r;
    r.x = (vm + 0.625f * (v0 - vm) - mn) * inv;
    r.y = (vm + 0.875f * (v0 - vm) - mn) * inv;
    r.z = (v0 + 0.125f * (vp - v0) - mn) * inv;
    r.w = (v0 + 0.375f * (vp - v0) - mn) * inv;

    *(float4*)(out + (n * 224 + y) * 224 + 4 * q) = r;
}

extern "C" void kernel_launch(void* const* d_in, const int* in_sizes, int n_in,
                              void* d_out, int out_size)
{
    const float* fmaps = (const float*)d_in[0];
    const int*   sel   = (const int*)  d_in[1];
    const float* mean  = (const float*)d_in[2];
    const float* cov   = (const float*)d_in[3];
    const float* mn    = (const float*)d_in[4];
    const float* mx    = (const float*)d_in[5];
    float* out = (float*)d_out;

    const int smem = C * 4 * P2 * 4 * sizeof(float);  // 204800 B
    cudaFuncSetAttribute(padim_main, cudaFuncAttributeMaxDynamicSharedMemorySize, smem);

    dim3 grid(HW / P, 3);
    padim_main<<<grid, NTHR, smem>>>(fmaps, sel, mean, cov);

    padim_smap<<<(NB * HW + 255) / 256, 256>>>();

    int total = NB * 224 * 56;
    padim_finalize<<<(total + 255) / 256, 256>>>(out, mn, mx);
}

// round 9
// speedup vs baseline: 2.7152x; 1.1857x over previous
#include <cuda_runtime.h>

// PaDiM Mahalanobis score map, GB300 sm_103a.
// Inputs (metadata order):
//   d_in[0] fmaps  f32 (8,448,56,56)
//   d_in[1] select int32 (100)
//   d_in[2] mean   f32 (100,56,56)
//   d_in[3] cov    f32 (100,100,56,56)  -- symmetric per pixel (A A^T)
//   d_in[4] min_score f32 scalar
//   d_in[5] max_score f32 scalar
// Output: f32 (8,224,224)

#define CT   448
#define C    100
#define HW   3136      // 56*56
#define NB   8
#define P    64        // pixels per block
#define NTHR 1024
#define NSL  24        // total d-slices (3 chunks x 8)
#define TOTS 2450      // total off-diagonal steps at 2-channel blocking
#define CHW  (C*HW)    // 313600

typedef unsigned long long u64;

// partial s^2 sums: [chunk][n][pixel]
__device__ float g_part[3 * NB * HW];
// sqrt'ed score map: [n][pixel]
__device__ float g_smap[NB * HW];

__device__ __forceinline__ u64 pk2(float lo, float hi) {
    u64 r; asm("mov.b64 %0, {%1, %2};" : "=l"(r) : "f"(lo), "f"(hi)); return r;
}
__device__ __forceinline__ float2 upk2(u64 a) {
    float2 f; asm("mov.b64 {%0, %1}, %2;" : "=f"(f.x), "=f"(f.y) : "l"(a)); return f;
}
__device__ __forceinline__ u64 add2(u64 a, u64 b) {
    u64 r; asm("add.rn.f32x2 %0, %1, %2;" : "=l"(r) : "l"(a), "l"(b)); return r;
}
__device__ __forceinline__ u64 mul2(u64 a, u64 b) {
    u64 r; asm("mul.rn.f32x2 %0, %1, %2;" : "=l"(r) : "l"(a), "l"(b)); return r;
}
__device__ __forceinline__ u64 fma2(u64 a, u64 b, u64 c) {
    u64 r; asm("fma.rn.f32x2 %0, %1, %2, %3;" : "=l"(r) : "l"(a), "l"(b), "l"(c)); return r;
}

// x tile: [c][p][n], n contiguous (32B per (c,p)).  100*64*8*4 = 204800 B
extern __shared__ float xs[];

__global__ void __launch_bounds__(NTHR, 1) padim_main(
    const float* __restrict__ fmaps,
    const int*   __restrict__ sel,
    const float* __restrict__ mean,
    const float* __restrict__ cov)
{
    __shared__ int sel_s[C];
    const int tid   = threadIdx.x;
    const int pbase = blockIdx.x * P;
    const int chunk = blockIdx.y;

    if (tid < C) sel_s[tid] = sel[tid];
    __syncthreads();

    // Build x tile (p fastest across lanes -> coalesced fmaps/mean loads)
    for (int i = tid; i < C * NB * P; i += NTHR) {
        int p = i & (P - 1);
        int n = (i >> 6) & 7;
        int c = i >> 9;
        float v = fmaps[(n * CT + sel_s[c]) * HW + pbase + p]
                - mean[c * HW + pbase + p];
        xs[(c * P + p) * 8 + n] = v;
    }
    __syncthreads();

    // thread mapping: lane = p_lo(16) + 16*nq  -> the 2 nq threads sharing a
    // cov value sit in the same warp; the coalescer merges their requests.
    const int lane = tid & 31;
    const int w    = tid >> 5;
    const int p    = (lane & 15) + 16 * (w & 3);  // pixel in tile (0..63)
    const int nq   = lane >> 4;                   // n quad: n in [4nq, 4nq+3]
    const int ds   = w >> 2;                      // 0..7
    const int slice = chunk * 8 + ds;             // 0..23
    const int pg   = pbase + p;
    const int xoff = 4 * nq;

    u64 acc0 = 0ull, acc1 = 0ull;   // packed accum: pair0 = (4nq,4nq+1), pair1

    // ---- off-diagonal sweep, 2-channel blocking ----
    // k-block k covers channels (2k, 2k+1), d in [2k+2, 99]: 98-2k steps.
    // base(k) = k*(99-k); total 2450 steps split into 24 slices.
    int g    = (slice * TOTS) / NSL;
    int gend = ((slice + 1) * TOTS) / NSL;
    int k = 0;
    while ((k + 1) * (98 - k) <= g) ++k;

    while (g < gend) {
        const int c0  = 2 * k;
        const int d0  = c0 + 2 + (g - k * (99 - k));
        const int nst = min(100 - d0, gend - g);

        float4 xa = *(const float4*)&xs[(c0 * P + p) * 8 + xoff];
        float4 xb = *(const float4*)&xs[((c0 + 1) * P + p) * 8 + xoff];
        u64 xc2_0p0 = pk2(xa.x + xa.x, xa.y + xa.y);
        u64 xc2_0p1 = pk2(xa.z + xa.z, xa.w + xa.w);
        u64 xc2_1p0 = pk2(xb.x + xb.x, xb.y + xb.y);
        u64 xc2_1p1 = pk2(xb.z + xb.z, xb.w + xb.w);

        u64 l00 = 0ull, l01 = 0ull, l10 = 0ull, l11 = 0ull;
        const float* cb = cov + (size_t)c0 * CHW + (size_t)d0 * HW + pg;

        #pragma unroll 4
        for (int s = 0; s < nst; ++s) {
            float v0 = __ldcs(cb);
            float v1 = __ldcs(cb + CHW);
            float4 xq = *(const float4*)&xs[((d0 + s) * P + p) * 8 + xoff];
            u64 xd0 = pk2(xq.x, xq.y);
            u64 xd1 = pk2(xq.z, xq.w);
            u64 dv0 = pk2(v0, v0);
            u64 dv1 = pk2(v1, v1);
            l00 = fma2(dv0, xd0, l00);
            l01 = fma2(dv0, xd1, l01);
            l10 = fma2(dv1, xd0, l10);
            l11 = fma2(dv1, xd1, l11);
            cb += HW;
        }

        acc0 = fma2(xc2_0p0, l00, acc0);
        acc0 = fma2(xc2_1p0, l10, acc0);
        acc1 = fma2(xc2_0p1, l01, acc1);
        acc1 = fma2(xc2_1p1, l11, acc1);

        g += nst;
        if (d0 + nst == 100) ++k;
    }

    // ---- diagonal 2x2 micro-blocks: block kk handled by slice kk%24 ----
    for (int kk = slice; kk < 50; kk += NSL) {
        const int c0 = 2 * kk;
        float4 xa = *(const float4*)&xs[(c0 * P + p) * 8 + xoff];
        float4 xb = *(const float4*)&xs[((c0 + 1) * P + p) * 8 + xoff];
        const float* cb = cov + (size_t)c0 * CHW + (size_t)c0 * HW + pg;
        float v00 = __ldcs(cb);                 // (c0,   c0)
        float v01 = __ldcs(cb + HW);            // (c0,   c0+1)
        float v11 = __ldcs(cb + CHW + HW);      // (c0+1, c0+1)
        u64 x0p0 = pk2(xa.x, xa.y), x0p1 = pk2(xa.z, xa.w);
        u64 x1p0 = pk2(xb.x, xb.y), x1p1 = pk2(xb.z, xb.w);
        u64 d00 = pk2(v00, v00);
        u64 d01 = pk2(v01 + v01, v01 + v01);
        u64 d11 = pk2(v11, v11);
        acc0 = fma2(d00, mul2(x0p0, x0p0), acc0);
        acc0 = fma2(d01, mul2(x0p0, x1p0), acc0);
        acc0 = fma2(d11, mul2(x1p0, x1p0), acc0);
        acc1 = fma2(d00, mul2(x0p1, x0p1), acc1);
        acc1 = fma2(d01, mul2(x0p1, x1p1), acc1);
        acc1 = fma2(d11, mul2(x1p1, x1p1), acc1);
    }

    // ---- in-block reduction over the 8 d-slices ----
    __syncthreads();                 // all xs reads done
    u64* red = (u64*)xs;
    red[tid * 2]     = acc0;
    red[tid * 2 + 1] = acc1;
    __syncthreads();

    if (tid < 128) {
        u64 a = red[tid * 2], b = red[tid * 2 + 1];
        #pragma unroll
        for (int s2 = 1; s2 < 8; ++s2) {
            a = add2(a, red[(tid + 128 * s2) * 2]);
            b = add2(b, red[(tid + 128 * s2) * 2 + 1]);
        }
        float2 r0 = upk2(a), r1 = upk2(b);
        int pr  = (tid & 15) + 16 * ((tid >> 5) & 3);   // pixel
        int nqr = (tid >> 4) & 1;
        int base = (chunk * NB + 4 * nqr) * HW + pbase + pr;
        g_part[base]          = r0.x;
        g_part[base + HW]     = r0.y;
        g_part[base + 2 * HW] = r1.x;
        g_part[base + 3 * HW] = r1.y;
    }
}

// sum 3 partials -> sqrt
__global__ void padim_smap()
{
    int i = blockIdx.x * blockDim.x + threadIdx.x;
    if (i >= NB * HW) return;
    float s2 = g_part[i] + g_part[NB * HW + i] + g_part[2 * NB * HW + i];
    g_smap[i] = sqrtf(fmaxf(s2, 0.0f));
}

// half-pixel bilinear x4 + normalize; 4 output x per thread
__global__ void padim_finalize(float* __restrict__ out,
                               const float* __restrict__ minp,
                               const float* __restrict__ maxp)
{
    int idx = blockIdx.x * blockDim.x + threadIdx.x;  // over NB*224*56
    if (idx >= NB * 224 * 56) return;
    int q = idx % 56;
    int t = idx / 56;
    int y = t % 224;
    int n = t / 224;

    float sy = y * 0.25f - 0.375f;
    float fy = floorf(sy);
    float wy = sy - fy;
    int y0 = max((int)fy, 0);
    int y1 = min((int)fy + 1, 55);
    int cm = max(q - 1, 0);
    int cp = min(q + 1, 55);

    const float* s = g_smap + n * HW;
    float sm0 = s[y0 * 56 + cm], sm1 = s[y1 * 56 + cm];
    float s00 = s[y0 * 56 + q],  s01 = s[y1 * 56 + q];
    float sp0 = s[y0 * 56 + cp], sp1 = s[y1 * 56 + cp];

    float vm = sm0 + wy * (sm1 - sm0);
    float v0 = s00 + wy * (s01 - s00);
    float vp = sp0 + wy * (sp1 - sp0);

    float mn  = *minp;
    float inv = 1.0f / (*maxp - mn);

    float4 r;
    r.x = (vm + 0.625f * (v0 - vm) - mn) * inv;
    r.y = (vm + 0.875f * (v0 - vm) - mn) * inv;
    r.z = (v0 + 0.125f * (vp - v0) - mn) * inv;
    r.w = (v0 + 0.375f * (vp - v0) - mn) * inv;

    *(float4*)(out + (n * 224 + y) * 224 + 4 * q) = r;
}

extern "C" void kernel_launch(void* const* d_in, const int* in_sizes, int n_in,
                              void* d_out, int out_size)
{
    const float* fmaps = (const float*)d_in[0];
    const int*   sel   = (const int*)  d_in[1];
    const float* mean  = (const float*)d_in[2];
    const float* cov   = (const float*)d_in[3];
    const float* mn    = (const float*)d_in[4];
    const float* mx    = (const float*)d_in[5];
    float* out = (float*)d_out;

    const int smem = C * P * 8 * sizeof(float);  // 204800 B
    cudaFuncSetAttribute(padim_main, cudaFuncAttributeMaxDynamicSharedMemorySize, smem);

    dim3 grid(HW / P, 3);
    padim_main<<<grid, NTHR, smem>>>(fmaps, sel, mean, cov);

    padim_smap<<<(NB * HW + 255) / 256, 256>>>();

    int total = NB * 224 * 56;
    padim_finalize<<<(total + 255) / 256, 256>>>(out, mn, mx);
}